// round 1
// baseline (speedup 1.0000x reference)
#include <cuda_runtime.h>
#include <cuda_bf16.h>

// MedSegNetV2: 3x3 windowed texture features + martingale transform.
// x: [8, 64, 224, 224] f32  ->  out: [8, 256, 224, 224] f32 (channel = c*4 + feature)
//
// Features over the zero-padded 3x3 window p[0..8], m = mean(p):
//   contrast    = M2 / (9*std_c^2), std_c = max(sqrt(M2/8), 1e-3)
//               = 8/9 exactly when var >= 1e-6, else M2/(9e-6)
//   energy      = (1/9) * sum p^2
//   entropy     = -(1/9) * sum c*log(c), c = max(p, 1e-6)   [separable -> precompute]
//   homogeneity = 9 / (9 + sum|p-m| + 9e-6)
// martingale(f) = clamp(max(f,1e-5) * exp(-0.5), 1e-4, 1e4)

#define IMG_H 224
#define IMG_W 224
#define PLANE (IMG_H * IMG_W)
#define TW 32
#define TH 8

__global__ void __launch_bounds__(TW * TH)
medsegnet_kernel(const float* __restrict__ x, float* __restrict__ out) {
    __shared__ float sp[TH + 2][TW + 2];   // raw values (with halo)
    __shared__ float sl[TH + 2][TW + 2];   // c*log(c) values (with halo)

    const int plane = blockIdx.z;                 // b*64 + c
    const int tx = threadIdx.x, ty = threadIdx.y;
    const int x0 = blockIdx.x * TW;
    const int y0 = blockIdx.y * TH;

    const float* __restrict__ base = x + (size_t)plane * PLANE;

    // Cooperative halo-tile load + one plogp per element (not 9x per pixel).
    const int tid = ty * TW + tx;
    #pragma unroll
    for (int i = tid; i < (TH + 2) * (TW + 2); i += TW * TH) {
        const int rr = i / (TW + 2);
        const int cc = i - rr * (TW + 2);
        const int gr = y0 + rr - 1;
        const int gc = x0 + cc - 1;
        float v = 0.0f;
        if (gr >= 0 && gr < IMG_H && gc >= 0 && gc < IMG_W)
            v = __ldg(base + gr * IMG_W + gc);
        sp[rr][cc] = v;
        const float c = fmaxf(v, 1e-6f);
        sl[rr][cc] = c * __logf(c);
    }
    __syncthreads();

    // Gather the 3x3 window for this pixel (conflict-free LDS).
    float p[9];
    float S1 = 0.0f, S2 = 0.0f, SL = 0.0f;
    #pragma unroll
    for (int dy = 0; dy < 3; dy++) {
        #pragma unroll
        for (int dx = 0; dx < 3; dx++) {
            const float v = sp[ty + dy][tx + dx];
            p[dy * 3 + dx] = v;
            S1 += v;
            S2 = fmaf(v, v, S2);
            SL += sl[ty + dy][tx + dx];
        }
    }

    const float m = S1 * (1.0f / 9.0f);
    float M2 = 0.0f, sad = 0.0f;
    #pragma unroll
    for (int i = 0; i < 9; i++) {
        const float d = p[i] - m;
        M2 = fmaf(d, d, M2);
        sad += fabsf(d);
    }

    const float var = M2 * 0.125f;                       // ddof=1 over 9 samples
    const float contrast = (var >= 1e-6f) ? (8.0f / 9.0f)
                                          : (M2 * (1.0f / 9e-6f));
    const float energy  = S2 * (1.0f / 9.0f);
    const float entropy = -SL * (1.0f / 9.0f);
    const float homog   = 9.0f * __frcp_rn(9.0f + sad + 9e-6f);

    // martingale: exp(1*log(clip(f,1e-5)) - 0.5) == clip(f,1e-5)*e^-0.5, then clamp
    const float C = 0.6065306597126334f;                 // exp(-0.5)
    #define MART(f) fminf(fmaxf(fmaxf((f), 1e-5f) * C, 1e-4f), 1e4f)
    const float f0 = MART(contrast);
    const float f1 = MART(energy);
    const float f2 = MART(entropy);
    const float f3 = MART(homog);
    #undef MART

    const size_t pix = (size_t)(y0 + ty) * IMG_W + (x0 + tx);
    float* __restrict__ o = out + (size_t)plane * 4 * PLANE + pix;
    o[0 * PLANE] = f0;
    o[1 * PLANE] = f1;
    o[2 * PLANE] = f2;
    o[3 * PLANE] = f3;
}

extern "C" void kernel_launch(void* const* d_in, const int* in_sizes, int n_in,
                              void* d_out, int out_size) {
    const float* x = (const float*)d_in[0];
    float* out = (float*)d_out;
    // x: [8, 64, 224, 224] -> 512 planes; 224 = 7*32 = 28*8 (no ragged tiles)
    dim3 block(TW, TH);
    dim3 grid(IMG_W / TW, IMG_H / TH, 512);
    medsegnet_kernel<<<grid, block>>>(x, out);
}

// round 2
// speedup vs baseline: 1.1530x; 1.1530x over previous
#include <cuda_runtime.h>
#include <cuda_bf16.h>

// MedSegNetV2: 3x3 texture features + martingale, vectorized 4 px/thread.
// x: [8,64,224,224] f32 -> out: [8,256,224,224] f32, channel = c*4 + feature.
//
// Closed forms (verified R1, rel_err 1e-7):
//   contrast = 8/9 if M2 >= 8e-6 else M2/9e-6        (M2 = S2 - S1^2/9)
//   energy = S2/9;  entropy = -SL/9 (SL = sum c*log c, c=max(p,1e-6))
//   homog = 9/(9 + sad + 9e-6)
//   mart(f) = clamp(f*exp(-0.5), 1e-4, 1e4)   [1e-5 pre-clip dominated by 1e-4]

#define IMG_H 224
#define IMG_W 224
#define PLANE (IMG_H * IMG_W)
#define BX 56            // threads in x, 4 px each -> full 224-wide row
#define BY 4             // output rows per block
#define NTHR (BX * BY)
#define SROWS (BY + 2)

__global__ void __launch_bounds__(NTHR)
medseg2_kernel(const float* __restrict__ x, float* __restrict__ out) {
    __shared__ float sp[SROWS][IMG_W];   // raw values
    __shared__ float sl[SROWS][IMG_W];   // c*log(c)

    const int tx = threadIdx.x, ty = threadIdx.y;
    const int tid = ty * BX + tx;
    const int lane = tid & 31;
    const int y0 = blockIdx.y * BY;
    const int plane = blockIdx.z;

    const float* __restrict__ base = x + (size_t)plane * PLANE;
    const float PL0 = -1.3815511e-5f;    // 1e-6 * ln(1e-6) = plogp(padded zero)

    // ---- Phase 1: load 6 rows x 224 cols as float4, precompute plogp once ----
    #pragma unroll 2
    for (int i = tid; i < SROWS * (IMG_W / 4); i += NTHR) {
        const int r = i / (IMG_W / 4);
        const int c4 = i - r * (IMG_W / 4);
        const int gr = y0 + r - 1;
        float4 v = make_float4(0.f, 0.f, 0.f, 0.f);
        if (gr >= 0 && gr < IMG_H)
            v = *(const float4*)(base + gr * IMG_W + c4 * 4);
        ((float4*)sp[r])[c4] = v;
        float4 l;
        float c;
        c = fmaxf(v.x, 1e-6f); l.x = c * __logf(c);
        c = fmaxf(v.y, 1e-6f); l.y = c * __logf(c);
        c = fmaxf(v.z, 1e-6f); l.z = c * __logf(c);
        c = fmaxf(v.w, 1e-6f); l.w = c * __logf(c);
        ((float4*)sl[r])[c4] = l;
    }
    __syncthreads();

    // ---- Phase 2: column sums over 6 cols x 3 rows, via LDS.128 + shfl ----
    float cS1[6], cS2[6], cSL[6];
    float pr[3][6];
    #pragma unroll
    for (int j = 0; j < 6; j++) { cS1[j] = 0.f; cS2[j] = 0.f; cSL[j] = 0.f; }

    const unsigned FULL = 0xFFFFFFFFu;
    #pragma unroll
    for (int r = 0; r < 3; r++) {
        const float4 cp = ((const float4*)sp[ty + r])[tx];
        const float4 cl = ((const float4*)sl[ty + r])[tx];
        float lp = __shfl_up_sync(FULL, cp.w, 1);
        float ll = __shfl_up_sync(FULL, cl.w, 1);
        float rp = __shfl_down_sync(FULL, cp.x, 1);
        float rl = __shfl_down_sync(FULL, cl.x, 1);
        if (tx == 0)            { lp = 0.f; ll = PL0; }          // image pad
        else if (lane == 0)     { lp = sp[ty + r][4 * tx - 1];   // warp seam
                                  ll = sl[ty + r][4 * tx - 1]; }
        if (tx == BX - 1)       { rp = 0.f; rl = PL0; }
        else if (lane == 31)    { rp = sp[ty + r][4 * tx + 4];
                                  rl = sl[ty + r][4 * tx + 4]; }

        const float pv[6] = { lp, cp.x, cp.y, cp.z, cp.w, rp };
        const float lv[6] = { ll, cl.x, cl.y, cl.z, cl.w, rl };
        #pragma unroll
        for (int j = 0; j < 6; j++) {
            pr[r][j] = pv[j];
            cS1[j] += pv[j];
            cS2[j] = fmaf(pv[j], pv[j], cS2[j]);
            cSL[j] += lv[j];
        }
    }

    // ---- Per-pixel features (4 px) ----
    const float C   = 0.6065306597126334f;     // exp(-0.5)
    const float K1  = (8.0f / 9.0f) * C;       // contrast (normal branch), in clamp range
    const float KC0 = C / 9e-6f;               // contrast (tiny-var branch)
    const float KE  = C / 9.0f;
    const float KH  = 9.0f * C;

    float g0[4], g1[4], g2[4], g3[4];
    #pragma unroll
    for (int j = 0; j < 4; j++) {
        const float S1 = cS1[j] + cS1[j + 1] + cS1[j + 2];
        const float S2 = cS2[j] + cS2[j + 1] + cS2[j + 2];
        const float SL = cSL[j] + cSL[j + 1] + cSL[j + 2];
        const float m  = S1 * (1.0f / 9.0f);
        const float M2 = fmaf(-S1, m, S2);

        float sad = 0.f;
        #pragma unroll
        for (int r = 0; r < 3; r++)
            #pragma unroll
            for (int k = 0; k < 3; k++)
                sad += fabsf(pr[r][j + k] - m);

        g0[j] = (M2 >= 8e-6f) ? K1 : fmaxf(M2 * KC0, 1e-4f);
        g1[j] = fminf(fmaxf(S2 * KE, 1e-4f), 1e4f);
        g2[j] = fminf(fmaxf(SL * (-KE), 1e-4f), 1e4f);
        g3[j] = fminf(fmaxf(KH * __frcp_rn(9.0f + sad + 9e-6f), 1e-4f), 1e4f);
    }

    // ---- Vectorized stores: one STG.128 per feature plane ----
    const int row = y0 + ty;
    float* __restrict__ o = out + (size_t)plane * 4 * PLANE + row * IMG_W + 4 * tx;
    *(float4*)(o + 0 * PLANE) = make_float4(g0[0], g0[1], g0[2], g0[3]);
    *(float4*)(o + 1 * PLANE) = make_float4(g1[0], g1[1], g1[2], g1[3]);
    *(float4*)(o + 2 * PLANE) = make_float4(g2[0], g2[1], g2[2], g2[3]);
    *(float4*)(o + 3 * PLANE) = make_float4(g3[0], g3[1], g3[2], g3[3]);
}

extern "C" void kernel_launch(void* const* d_in, const int* in_sizes, int n_in,
                              void* d_out, int out_size) {
    const float* x = (const float*)d_in[0];
    float* out = (float*)d_out;
    dim3 block(BX, BY);                 // 224 threads
    dim3 grid(1, IMG_H / BY, 512);      // 56 row-strips x 512 planes
    medseg2_kernel<<<grid, block>>>(x, out);
}

// round 3
// speedup vs baseline: 1.2689x; 1.1005x over previous
#include <cuda_runtime.h>
#include <cuda_bf16.h>

// MedSegNetV2: 3x3 texture features + martingale. 4 px/thread, branchless seams,
// SAD re-read from smem (no pr[] register array), padded smem columns.
// x: [8,64,224,224] f32 -> out: [8,256,224,224] f32, channel = c*4 + feature.

#define IMG_H 224
#define IMG_W 224
#define PLANE (IMG_H * IMG_W)
#define BX 56
#define BY 4
#define NTHR (BX * BY)
#define SROWS (BY + 2)
#define SW 232                    // padded row stride (floats); data at [4..227+4]

__global__ void __launch_bounds__(NTHR, 6)
medseg3_kernel(const float* __restrict__ x, float* __restrict__ out) {
    __shared__ float sp[SROWS][SW];   // raw values, data offset +4, pads at [3],[228]
    __shared__ float sl[SROWS][SW];   // c*log(c)

    const int tx = threadIdx.x, ty = threadIdx.y;
    const int tid = ty * BX + tx;
    const int lane = tid & 31;
    const int y0 = blockIdx.y * BY;
    const int plane = blockIdx.z;

    const float* __restrict__ base = x + (size_t)plane * PLANE;
    const float PL0 = -1.3815511e-5f;          // 1e-6 * ln(1e-6)

    // Pad columns (left col -1 -> idx 3, right col 224 -> idx 228), every row.
    if (tid < 2 * SROWS) {
        const int r = tid >> 1;
        const int col = (tid & 1) ? 228 : 3;
        sp[r][col] = 0.0f;
        sl[r][col] = PL0;
    }

    // Tile load: 6 rows x 224 cols as float4; plogp computed once per element.
    #pragma unroll 2
    for (int i = tid; i < SROWS * (IMG_W / 4); i += NTHR) {
        const int r = i / (IMG_W / 4);
        const int c4 = i - r * (IMG_W / 4);
        const int gr = y0 + r - 1;
        float4 v = make_float4(0.f, 0.f, 0.f, 0.f);
        if (gr >= 0 && gr < IMG_H)
            v = *(const float4*)(base + gr * IMG_W + c4 * 4);
        ((float4*)&sp[r][4])[c4] = v;
        float4 l; float c;
        c = fmaxf(v.x, 1e-6f); l.x = c * __logf(c);
        c = fmaxf(v.y, 1e-6f); l.y = c * __logf(c);
        c = fmaxf(v.z, 1e-6f); l.z = c * __logf(c);
        c = fmaxf(v.w, 1e-6f); l.w = c * __logf(c);
        ((float4*)&sl[r][4])[c4] = l;
    }
    __syncthreads();

    // Seam predicates: exactly the lanes whose shfl source crosses a row seam
    // in the 56-wide thread layout (or the image border).
    const bool pL = (lane == 0) || (tx == 0);
    const bool pR = (lane == 31) || (tx == BX - 1);
    const unsigned FULL = 0xFFFFFFFFu;
    const int cb = 4 * tx;

    // ---- Pass 1: column sums over 6 cols x 3 rows ----
    float cS1[6], cS2[6], cSL[6];
    #pragma unroll
    for (int j = 0; j < 6; j++) { cS1[j] = 0.f; cS2[j] = 0.f; cSL[j] = 0.f; }

    #pragma unroll
    for (int r = 0; r < 3; r++) {
        const float* rowp = &sp[ty + r][cb];
        const float* rowl = &sl[ty + r][cb];
        const float4 cp = *(const float4*)(rowp + 4);
        const float4 cl = *(const float4*)(rowl + 4);
        float lp = __shfl_up_sync(FULL, cp.w, 1);   if (pL) lp = rowp[3];
        float ll = __shfl_up_sync(FULL, cl.w, 1);   if (pL) ll = rowl[3];
        float rv = __shfl_down_sync(FULL, cp.x, 1); if (pR) rv = rowp[8];
        float rl = __shfl_down_sync(FULL, cl.x, 1); if (pR) rl = rowl[8];

        const float pv[6] = { lp, cp.x, cp.y, cp.z, cp.w, rv };
        const float lv[6] = { ll, cl.x, cl.y, cl.z, cl.w, rl };
        #pragma unroll
        for (int j = 0; j < 6; j++) {
            cS1[j] += pv[j];
            cS2[j] = fmaf(pv[j], pv[j], cS2[j]);
            cSL[j] += lv[j];
        }
    }

    // Horizontal tri-sums via shared pair sums (9 adds per array).
    float S1[4], S2[4], SL[4], m[4], M2[4];
    {
        #pragma unroll
        for (int a = 0; a < 3; a++) {
            const float* c = (a == 0) ? cS1 : (a == 1) ? cS2 : cSL;
            float* s = (a == 0) ? S1 : (a == 1) ? S2 : SL;
            const float e1 = c[1] + c[2];
            const float e2 = c[2] + c[3];
            const float e3 = c[3] + c[4];
            s[0] = c[0] + e1;
            s[1] = e1 + c[3];   // c1+c2+c3
            s[2] = e2 + c[4];
            s[3] = e3 + c[5];
        }
        #pragma unroll
        for (int j = 0; j < 4; j++) {
            m[j] = S1[j] * (1.0f / 9.0f);
            M2[j] = fmaf(-S1[j], m[j], S2[j]);
        }
    }

    // ---- Pass 2: SAD (re-read raw rows; frees the 18-reg window array) ----
    float sad[4] = {0.f, 0.f, 0.f, 0.f};
    #pragma unroll
    for (int r = 0; r < 3; r++) {
        const float* rowp = &sp[ty + r][cb];
        const float4 cp = *(const float4*)(rowp + 4);
        float lp = __shfl_up_sync(FULL, cp.w, 1);   if (pL) lp = rowp[3];
        float rv = __shfl_down_sync(FULL, cp.x, 1); if (pR) rv = rowp[8];
        const float pv[6] = { lp, cp.x, cp.y, cp.z, cp.w, rv };
        #pragma unroll
        for (int j = 0; j < 4; j++) {
            sad[j] += fabsf(pv[j] - m[j]);
            sad[j] += fabsf(pv[j + 1] - m[j]);
            sad[j] += fabsf(pv[j + 2] - m[j]);
        }
    }

    // ---- Features + martingale (upper clamps provably never bind) ----
    const float C   = 0.6065306597126334f;   // exp(-0.5)
    const float K1  = (8.0f / 9.0f) * C;
    const float KC0 = C / 9e-6f;
    const float KE  = C / 9.0f;
    const float KH  = 9.0f * C;

    float g0[4], g1[4], g2[4], g3[4];
    #pragma unroll
    for (int j = 0; j < 4; j++) {
        g0[j] = (M2[j] >= 8e-6f) ? K1 : fmaxf(M2[j] * KC0, 1e-4f);
        g1[j] = fmaxf(S2[j] * KE, 1e-4f);
        g2[j] = fmaxf(SL[j] * (-KE), 1e-4f);
        g3[j] = fmaxf(KH * __frcp_rn(9.0f + sad[j] + 9e-6f), 1e-4f);
    }

    const int row = y0 + ty;
    float* __restrict__ o = out + (size_t)plane * 4 * PLANE + row * IMG_W + cb;
    *(float4*)(o + 0 * PLANE) = make_float4(g0[0], g0[1], g0[2], g0[3]);
    *(float4*)(o + 1 * PLANE) = make_float4(g1[0], g1[1], g1[2], g1[3]);
    *(float4*)(o + 2 * PLANE) = make_float4(g2[0], g2[1], g2[2], g2[3]);
    *(float4*)(o + 3 * PLANE) = make_float4(g3[0], g3[1], g3[2], g3[3]);
}

extern "C" void kernel_launch(void* const* d_in, const int* in_sizes, int n_in,
                              void* d_out, int out_size) {
    const float* x = (const float*)d_in[0];
    float* out = (float*)d_out;
    dim3 block(BX, BY);
    dim3 grid(1, IMG_H / BY, 512);
    medseg3_kernel<<<grid, block>>>(x, out);
}